// round 1
// baseline (speedup 1.0000x reference)
#include <cuda_runtime.h>

// out[b, t, h] = sum_{j=0..4} x[b, t+j, h] * a[b, t+j]
// x: (32, 1, 2052, 768) f32, a: (32, 2052) f32, out: (32, 1, 2048, 768) f32
//
// Strategy: HBM-bound streaming kernel. Each CTA handles (batch b, tile of TT
// t-positions). 192 threads each own one float4 (4 consecutive h). Slide a
// 5-entry register window of pre-weighted rows along t so every x element is
// fetched from DRAM exactly once, coalesced 16B per lane.

constexpr int LENGTH = 2048;
constexpr int WIDTH  = 5;
constexpr int H      = 768;
constexpr int PAD    = LENGTH + WIDTH - 1;   // 2052
constexpr int H4     = H / 4;                // 192
constexpr int TT     = 128;                  // t-positions per CTA
constexpr int B      = 32;

__global__ __launch_bounds__(H4) void widthap_kernel(
    const float* __restrict__ x,
    const float* __restrict__ att,
    float* __restrict__ out)
{
    const int b  = blockIdx.y;
    const int t0 = blockIdx.x * TT;
    const int h4 = threadIdx.x;          // 0..191

    __shared__ float sa[TT + WIDTH - 1]; // 132 weights for rows t0 .. t0+TT+3

    for (int i = threadIdx.x; i < TT + WIDTH - 1; i += blockDim.x)
        sa[i] = att[b * PAD + t0 + i];
    __syncthreads();

    const float4* __restrict__ xb =
        reinterpret_cast<const float4*>(x + (size_t)b * PAD * H) + h4;
    float4* __restrict__ ob =
        reinterpret_cast<float4*>(out + (size_t)b * LENGTH * H) + h4;

    // Prologue: load+weight first 4 rows of the window.
    float4 w0, w1, w2, w3;
    {
        float4 v;
        float a;
        v = xb[(size_t)(t0 + 0) * H4]; a = sa[0];
        w0 = make_float4(v.x * a, v.y * a, v.z * a, v.w * a);
        v = xb[(size_t)(t0 + 1) * H4]; a = sa[1];
        w1 = make_float4(v.x * a, v.y * a, v.z * a, v.w * a);
        v = xb[(size_t)(t0 + 2) * H4]; a = sa[2];
        w2 = make_float4(v.x * a, v.y * a, v.z * a, v.w * a);
        v = xb[(size_t)(t0 + 3) * H4]; a = sa[3];
        w3 = make_float4(v.x * a, v.y * a, v.z * a, v.w * a);
    }

    #pragma unroll 4
    for (int i = 0; i < TT; i++) {
        float4 v = xb[(size_t)(t0 + i + 4) * H4];
        float  a = sa[i + 4];
        float4 w4 = make_float4(v.x * a, v.y * a, v.z * a, v.w * a);

        float4 s;
        s.x = w0.x + w1.x + w2.x + w3.x + w4.x;
        s.y = w0.y + w1.y + w2.y + w3.y + w4.y;
        s.z = w0.z + w1.z + w2.z + w3.z + w4.z;
        s.w = w0.w + w1.w + w2.w + w3.w + w4.w;

        ob[(size_t)(t0 + i) * H4] = s;

        w0 = w1; w1 = w2; w2 = w3; w3 = w4;
    }
}

extern "C" void kernel_launch(void* const* d_in, const int* in_sizes, int n_in,
                              void* d_out, int out_size)
{
    const float* x   = (const float*)d_in[0];       // (32,1,2052,768)
    const float* att = (const float*)d_in[1];       // (32,2052)
    float* out       = (float*)d_out;               // (32,1,2048,768)

    dim3 grid(LENGTH / TT, B);   // (16, 32) = 512 CTAs
    dim3 block(H4);              // 192 threads
    widthap_kernel<<<grid, block>>>(x, att, out);
}